// round 2
// baseline (speedup 1.0000x reference)
#include <cuda_runtime.h>

#define NN 50000
#define EE 800000

// Scratch (allocation-free rule: __device__ globals)
__device__ float g_feat[NN * 64];
__device__ float g_el[NN * 4];
__device__ float g_er[NN * 4];
__device__ int   g_idx64;     // 1 if src/dst are int64, 0 if int32

// ---------------------------------------------------------------------------
// Probe: detect whether index arrays are int64 or int32.
// Node ids < 2^31, so int64 encoding has zero high words at odd 32-bit slots.
// ---------------------------------------------------------------------------
__global__ void probe_kernel(const unsigned* __restrict__ src_words)
{
    g_idx64 = (src_words[1] == 0u && src_words[3] == 0u &&
               src_words[5] == 0u && src_words[7] == 0u) ? 1 : 0;
}

// ---------------------------------------------------------------------------
// Node kernel: feat = h@W_fc, el/er head-dots, out = h@W_res (resval).
// Block = 256 threads = 64 groups x 4 heads; each group handles 4 nodes.
// SMEM: sW[64*64] (current W matrix) + sT[64*256] (h tile, transposed).
// ---------------------------------------------------------------------------
__global__ __launch_bounds__(256, 2)
void node_kernel(const float* __restrict__ h,
                 const float* __restrict__ Wfc,
                 const float* __restrict__ Wres,
                 const float* __restrict__ al,
                 const float* __restrict__ ar,
                 float* __restrict__ out)
{
    extern __shared__ float smem[];
    float* sW = smem;          // 4096 floats (16 KB)
    float* sT = smem + 4096;   // 64 x 256 floats (64 KB), sT[k*256 + node_local]

    const int t   = threadIdx.x;
    const int nb0 = blockIdx.x * 256;

    // Stage W_fc (coalesced)
    #pragma unroll
    for (int i = 0; i < 16; i++) sW[i * 256 + t] = Wfc[i * 256 + t];

    // Stage h tile transposed: thread t owns node nb0+t
    {
        const int n = nb0 + t;
        #pragma unroll
        for (int k4 = 0; k4 < 16; k4++) {
            float4 v = make_float4(0.f, 0.f, 0.f, 0.f);
            if (n < NN) v = reinterpret_cast<const float4*>(h)[n * 16 + k4];
            sT[(k4 * 4 + 0) * 256 + t] = v.x;
            sT[(k4 * 4 + 1) * 256 + t] = v.y;
            sT[(k4 * 4 + 2) * 256 + t] = v.z;
            sT[(k4 * 4 + 3) * 256 + t] = v.w;
        }
    }
    __syncthreads();

    const int g    = t >> 2;   // group (4 nodes)
    const int head = t & 3;    // output column block = head*16 .. head*16+15

    const float4* sT4 = reinterpret_cast<const float4*>(sT);
    const float4* sW4 = reinterpret_cast<const float4*>(sW);

    float acc[4][16];

    // ---------------- Phase 1: feat = h @ W_fc ----------------
    #pragma unroll
    for (int i = 0; i < 4; i++)
        #pragma unroll
        for (int j = 0; j < 16; j++) acc[i][j] = 0.f;

    #pragma unroll 4
    for (int k = 0; k < 64; k++) {
        float4 hv = sT4[k * 64 + g];          // 4 nodes' h[k] (broadcast per quad)
        float hvv[4] = {hv.x, hv.y, hv.z, hv.w};
        #pragma unroll
        for (int jq = 0; jq < 4; jq++) {
            float4 w = sW4[k * 16 + head * 4 + jq];
            #pragma unroll
            for (int i = 0; i < 4; i++) {
                acc[i][jq * 4 + 0] += hvv[i] * w.x;
                acc[i][jq * 4 + 1] += hvv[i] * w.y;
                acc[i][jq * 4 + 2] += hvv[i] * w.z;
                acc[i][jq * 4 + 3] += hvv[i] * w.w;
            }
        }
    }

    // Epilogue 1: write feat, el, er
    {
        float alr[16], arr[16];
        #pragma unroll
        for (int j = 0; j < 16; j++) {
            alr[j] = __ldg(&al[head * 16 + j]);
            arr[j] = __ldg(&ar[head * 16 + j]);
        }
        #pragma unroll
        for (int i = 0; i < 4; i++) {
            const int n = nb0 + g * 4 + i;
            if (n < NN) {
                float elv = 0.f, erv = 0.f;
                #pragma unroll
                for (int j = 0; j < 16; j++) {
                    elv += acc[i][j] * alr[j];
                    erv += acc[i][j] * arr[j];
                }
                float4* fp = reinterpret_cast<float4*>(&g_feat[n * 64 + head * 16]);
                #pragma unroll
                for (int jq = 0; jq < 4; jq++)
                    fp[jq] = make_float4(acc[i][jq * 4 + 0], acc[i][jq * 4 + 1],
                                         acc[i][jq * 4 + 2], acc[i][jq * 4 + 3]);
                g_el[n * 4 + head] = elv;
                g_er[n * 4 + head] = erv;
            }
        }
    }

    __syncthreads();
    // Stage W_res
    #pragma unroll
    for (int i = 0; i < 16; i++) sW[i * 256 + t] = Wres[i * 256 + t];
    __syncthreads();

    // ---------------- Phase 2: resval = h @ W_res ----------------
    #pragma unroll
    for (int i = 0; i < 4; i++)
        #pragma unroll
        for (int j = 0; j < 16; j++) acc[i][j] = 0.f;

    #pragma unroll 4
    for (int k = 0; k < 64; k++) {
        float4 hv = sT4[k * 64 + g];
        float hvv[4] = {hv.x, hv.y, hv.z, hv.w};
        #pragma unroll
        for (int jq = 0; jq < 4; jq++) {
            float4 w = sW4[k * 16 + head * 4 + jq];
            #pragma unroll
            for (int i = 0; i < 4; i++) {
                acc[i][jq * 4 + 0] += hvv[i] * w.x;
                acc[i][jq * 4 + 1] += hvv[i] * w.y;
                acc[i][jq * 4 + 2] += hvv[i] * w.z;
                acc[i][jq * 4 + 3] += hvv[i] * w.w;
            }
        }
    }

    #pragma unroll
    for (int i = 0; i < 4; i++) {
        const int n = nb0 + g * 4 + i;
        if (n < NN) {
            float4* op = reinterpret_cast<float4*>(&out[n * 64 + head * 16]);
            #pragma unroll
            for (int jq = 0; jq < 4; jq++)
                op[jq] = make_float4(acc[i][jq * 4 + 0], acc[i][jq * 4 + 1],
                                     acc[i][jq * 4 + 2], acc[i][jq * 4 + 3]);
        }
    }
}

// ---------------------------------------------------------------------------
// Edge kernel: 4 threads per edge (one per head). Head-softmax via quad
// shuffles; scatter with vector reductions (red.global.add.v4.f32).
// Index dtype (int32 vs int64) selected via g_idx64 set by probe_kernel.
// ---------------------------------------------------------------------------
__global__ __launch_bounds__(256)
void edge_kernel(const void* __restrict__ src_raw,
                 const void* __restrict__ dst_raw,
                 float* __restrict__ out)
{
    const int t = blockIdx.x * 256 + threadIdx.x;
    const int e = t >> 2;
    if (e >= EE) return;
    const int head = t & 3;

    int s, d;
    if (g_idx64) {
        s = (int)__ldg(&((const long long*)src_raw)[e]);
        d = (int)__ldg(&((const long long*)dst_raw)[e]);
    } else {
        s = __ldg(&((const int*)src_raw)[e]);
        d = __ldg(&((const int*)dst_raw)[e]);
    }

    float x = __ldg(&g_el[s * 4 + head]) + __ldg(&g_er[d * 4 + head]);
    x = (x > 0.f) ? x : 0.2f * x;                       // leaky relu

    // softmax over the 4 heads (lanes of this quad)
    float m = x;
    m = fmaxf(m, __shfl_xor_sync(0xFFFFFFFFu, m, 1));
    m = fmaxf(m, __shfl_xor_sync(0xFFFFFFFFu, m, 2));
    float p = __expf(x - m);
    float ssum = p;
    ssum += __shfl_xor_sync(0xFFFFFFFFu, ssum, 1);
    ssum += __shfl_xor_sync(0xFFFFFFFFu, ssum, 2);
    const float a = p / ssum;

    const float4* f4 = reinterpret_cast<const float4*>(&g_feat[s * 64 + head * 16]);
    float* o = out + d * 64 + head * 16;
    #pragma unroll
    for (int i = 0; i < 4; i++) {
        float4 v = f4[i];
        asm volatile("red.global.add.v4.f32 [%0], {%1,%2,%3,%4};"
                     :: "l"(o + i * 4),
                        "f"(v.x * a), "f"(v.y * a), "f"(v.z * a), "f"(v.w * a)
                     : "memory");
    }
}

// ---------------------------------------------------------------------------
extern "C" void kernel_launch(void* const* d_in, const int* in_sizes, int n_in,
                              void* d_out, int out_size)
{
    const float* h    = (const float*)d_in[0];
    const void*  src  = d_in[1];
    const void*  dst  = d_in[2];
    const float* Wfc  = (const float*)d_in[3];
    const float* al   = (const float*)d_in[4];
    const float* ar   = (const float*)d_in[5];
    const float* Wres = (const float*)d_in[6];
    float* out = (float*)d_out;

    probe_kernel<<<1, 1>>>((const unsigned*)src);

    const int smem_bytes = (4096 + 64 * 256) * sizeof(float);  // 80 KB
    cudaFuncSetAttribute(node_kernel, cudaFuncAttributeMaxDynamicSharedMemorySize,
                         smem_bytes);

    const int node_blocks = (NN + 255) / 256;        // 196
    node_kernel<<<node_blocks, 256, smem_bytes>>>(h, Wfc, Wres, al, ar, out);

    const int edge_blocks = (EE * 4) / 256;          // 12500 (exact)
    edge_kernel<<<edge_blocks, 256>>>(src, dst, out);
}

// round 3
// speedup vs baseline: 1.0127x; 1.0127x over previous
#include <cuda_runtime.h>

#define NN 50000
#define EE 800000

// Scratch (allocation-free rule: __device__ globals)
__device__ float g_feat[NN * 64];
__device__ float g_el[NN * 4];
__device__ float g_er[NN * 4];
__device__ int   g_idx64;     // 1 if src/dst are int64, 0 if int32

// ---------------------------------------------------------------------------
// Node kernel: feat = h@W_fc, el/er head-dots, out = h@W_res (resval).
// Block = 256 threads = 64 groups x 4 heads; each group handles 4 nodes.
// SMEM: sW[64*64] (current W matrix) + sT[64*256] (h tile, transposed).
// Block 0 / thread 0 additionally probes the index dtype (int32 vs int64):
// node ids < 2^31, so int64 encoding has zero high words at odd 32-bit slots.
// ---------------------------------------------------------------------------
__global__ __launch_bounds__(256, 2)
void node_kernel(const float* __restrict__ h,
                 const float* __restrict__ Wfc,
                 const float* __restrict__ Wres,
                 const float* __restrict__ al,
                 const float* __restrict__ ar,
                 float* __restrict__ out,
                 const unsigned* __restrict__ src_words)
{
    extern __shared__ float smem[];
    float* sW = smem;          // 4096 floats (16 KB)
    float* sT = smem + 4096;   // 64 x 256 floats (64 KB), sT[k*256 + node_local]

    const int t   = threadIdx.x;
    const int nb0 = blockIdx.x * 256;

    // Probe index dtype (done once; visible to edge_kernel via kernel boundary)
    if (blockIdx.x == 0 && t == 0) {
        g_idx64 = (src_words[1] == 0u && src_words[3] == 0u &&
                   src_words[5] == 0u && src_words[7] == 0u) ? 1 : 0;
    }

    // Stage W_fc (coalesced)
    #pragma unroll
    for (int i = 0; i < 16; i++) sW[i * 256 + t] = Wfc[i * 256 + t];

    // Stage h tile transposed: thread t owns node nb0+t
    {
        const int n = nb0 + t;
        #pragma unroll
        for (int k4 = 0; k4 < 16; k4++) {
            float4 v = make_float4(0.f, 0.f, 0.f, 0.f);
            if (n < NN) v = reinterpret_cast<const float4*>(h)[n * 16 + k4];
            sT[(k4 * 4 + 0) * 256 + t] = v.x;
            sT[(k4 * 4 + 1) * 256 + t] = v.y;
            sT[(k4 * 4 + 2) * 256 + t] = v.z;
            sT[(k4 * 4 + 3) * 256 + t] = v.w;
        }
    }
    __syncthreads();

    const int g    = t >> 2;   // group (4 nodes)
    const int head = t & 3;    // output column block = head*16 .. head*16+15

    const float4* sT4 = reinterpret_cast<const float4*>(sT);
    const float4* sW4 = reinterpret_cast<const float4*>(sW);

    float acc[4][16];

    // ---------------- Phase 1: feat = h @ W_fc ----------------
    #pragma unroll
    for (int i = 0; i < 4; i++)
        #pragma unroll
        for (int j = 0; j < 16; j++) acc[i][j] = 0.f;

    #pragma unroll 4
    for (int k = 0; k < 64; k++) {
        float4 hv = sT4[k * 64 + g];          // 4 nodes' h[k] (broadcast per quad)
        float hvv[4] = {hv.x, hv.y, hv.z, hv.w};
        #pragma unroll
        for (int jq = 0; jq < 4; jq++) {
            float4 w = sW4[k * 16 + head * 4 + jq];
            #pragma unroll
            for (int i = 0; i < 4; i++) {
                acc[i][jq * 4 + 0] += hvv[i] * w.x;
                acc[i][jq * 4 + 1] += hvv[i] * w.y;
                acc[i][jq * 4 + 2] += hvv[i] * w.z;
                acc[i][jq * 4 + 3] += hvv[i] * w.w;
            }
        }
    }

    // Epilogue 1: write feat, el, er
    {
        float alr[16], arr[16];
        #pragma unroll
        for (int j = 0; j < 16; j++) {
            alr[j] = __ldg(&al[head * 16 + j]);
            arr[j] = __ldg(&ar[head * 16 + j]);
        }
        #pragma unroll
        for (int i = 0; i < 4; i++) {
            const int n = nb0 + g * 4 + i;
            if (n < NN) {
                float elv = 0.f, erv = 0.f;
                #pragma unroll
                for (int j = 0; j < 16; j++) {
                    elv += acc[i][j] * alr[j];
                    erv += acc[i][j] * arr[j];
                }
                float4* fp = reinterpret_cast<float4*>(&g_feat[n * 64 + head * 16]);
                #pragma unroll
                for (int jq = 0; jq < 4; jq++)
                    fp[jq] = make_float4(acc[i][jq * 4 + 0], acc[i][jq * 4 + 1],
                                         acc[i][jq * 4 + 2], acc[i][jq * 4 + 3]);
                g_el[n * 4 + head] = elv;
                g_er[n * 4 + head] = erv;
            }
        }
    }

    __syncthreads();
    // Stage W_res
    #pragma unroll
    for (int i = 0; i < 16; i++) sW[i * 256 + t] = Wres[i * 256 + t];
    __syncthreads();

    // ---------------- Phase 2: resval = h @ W_res ----------------
    #pragma unroll
    for (int i = 0; i < 4; i++)
        #pragma unroll
        for (int j = 0; j < 16; j++) acc[i][j] = 0.f;

    #pragma unroll 4
    for (int k = 0; k < 64; k++) {
        float4 hv = sT4[k * 64 + g];
        float hvv[4] = {hv.x, hv.y, hv.z, hv.w};
        #pragma unroll
        for (int jq = 0; jq < 4; jq++) {
            float4 w = sW4[k * 16 + head * 4 + jq];
            #pragma unroll
            for (int i = 0; i < 4; i++) {
                acc[i][jq * 4 + 0] += hvv[i] * w.x;
                acc[i][jq * 4 + 1] += hvv[i] * w.y;
                acc[i][jq * 4 + 2] += hvv[i] * w.z;
                acc[i][jq * 4 + 3] += hvv[i] * w.w;
            }
        }
    }

    #pragma unroll
    for (int i = 0; i < 4; i++) {
        const int n = nb0 + g * 4 + i;
        if (n < NN) {
            float4* op = reinterpret_cast<float4*>(&out[n * 64 + head * 16]);
            #pragma unroll
            for (int jq = 0; jq < 4; jq++)
                op[jq] = make_float4(acc[i][jq * 4 + 0], acc[i][jq * 4 + 1],
                                     acc[i][jq * 4 + 2], acc[i][jq * 4 + 3]);
        }
    }
}

// ---------------------------------------------------------------------------
// Edge kernel: 4 threads per edge (one per head). Head-softmax via quad
// shuffles; scatter with vector reductions (red.global.add.v4.f32).
// Index dtype (int32 vs int64) selected via g_idx64 set in node_kernel.
// ---------------------------------------------------------------------------
__global__ __launch_bounds__(256)
void edge_kernel(const void* __restrict__ src_raw,
                 const void* __restrict__ dst_raw,
                 float* __restrict__ out)
{
    const int t = blockIdx.x * 256 + threadIdx.x;
    const int e = t >> 2;
    if (e >= EE) return;
    const int head = t & 3;

    int s, d;
    if (g_idx64) {
        s = (int)__ldg(&((const long long*)src_raw)[e]);
        d = (int)__ldg(&((const long long*)dst_raw)[e]);
    } else {
        s = __ldg(&((const int*)src_raw)[e]);
        d = __ldg(&((const int*)dst_raw)[e]);
    }

    float x = __ldg(&g_el[s * 4 + head]) + __ldg(&g_er[d * 4 + head]);
    x = (x > 0.f) ? x : 0.2f * x;                       // leaky relu

    // softmax over the 4 heads (lanes of this quad)
    float m = x;
    m = fmaxf(m, __shfl_xor_sync(0xFFFFFFFFu, m, 1));
    m = fmaxf(m, __shfl_xor_sync(0xFFFFFFFFu, m, 2));
    float p = __expf(x - m);
    float ssum = p;
    ssum += __shfl_xor_sync(0xFFFFFFFFu, ssum, 1);
    ssum += __shfl_xor_sync(0xFFFFFFFFu, ssum, 2);
    const float a = p / ssum;

    const float4* f4 = reinterpret_cast<const float4*>(&g_feat[s * 64 + head * 16]);
    float* o = out + d * 64 + head * 16;
    #pragma unroll
    for (int i = 0; i < 4; i++) {
        float4 v = f4[i];
        asm volatile("red.global.add.v4.f32 [%0], {%1,%2,%3,%4};"
                     :: "l"(o + i * 4),
                        "f"(v.x * a), "f"(v.y * a), "f"(v.z * a), "f"(v.w * a)
                     : "memory");
    }
}

// ---------------------------------------------------------------------------
extern "C" void kernel_launch(void* const* d_in, const int* in_sizes, int n_in,
                              void* d_out, int out_size)
{
    const float* h    = (const float*)d_in[0];
    const void*  src  = d_in[1];
    const void*  dst  = d_in[2];
    const float* Wfc  = (const float*)d_in[3];
    const float* al   = (const float*)d_in[4];
    const float* ar   = (const float*)d_in[5];
    const float* Wres = (const float*)d_in[6];
    float* out = (float*)d_out;

    const int smem_bytes = (4096 + 64 * 256) * sizeof(float);  // 80 KB
    cudaFuncSetAttribute(node_kernel, cudaFuncAttributeMaxDynamicSharedMemorySize,
                         smem_bytes);

    const int node_blocks = (NN + 255) / 256;        // 196
    node_kernel<<<node_blocks, 256, smem_bytes>>>(h, Wfc, Wres, al, ar, out,
                                                  (const unsigned*)src);

    const int edge_blocks = (EE * 4) / 256;          // 12500 (exact)
    edge_kernel<<<edge_blocks, 256>>>(src, dst, out);
}

// round 4
// speedup vs baseline: 1.0543x; 1.0410x over previous
#include <cuda_runtime.h>

#define NN 50000
#define EE 800000
#define NPB 128   // nodes per block (node kernel)

// Scratch (allocation-free rule: __device__ globals)
__device__ float g_feat[NN * 64];
__device__ float g_el[NN * 4];
__device__ float g_er[NN * 4];
__device__ int   g_idx64;     // 1 if src/dst are int64, 0 if int32

// ---------------------------------------------------------------------------
// Node kernel: feat = h@W_fc, el/er head-dots, out = h@W_res (resval).
// 128 nodes / block, 256 threads = 64 groups x 4 heads; group handles 2 nodes.
// SMEM: sW[64*64] (16 KB) + sT[64*128] transposed h tile (32 KB) -> occ 4.
// Block 0 / thread 0 probes index dtype (int32 vs int64): node ids < 2^31,
// so int64 encoding has zero high words at odd 32-bit slots.
// ---------------------------------------------------------------------------
__global__ __launch_bounds__(256, 4)
void node_kernel(const float* __restrict__ h,
                 const float* __restrict__ Wfc,
                 const float* __restrict__ Wres,
                 const float* __restrict__ al,
                 const float* __restrict__ ar,
                 float* __restrict__ out,
                 const unsigned* __restrict__ src_words)
{
    extern __shared__ float smem[];
    float* sW = smem;          // 4096 floats
    float* sT = smem + 4096;   // 64 x 128 floats, sT[k*128 + local]

    const int t   = threadIdx.x;
    const int nb0 = blockIdx.x * NPB;

    if (blockIdx.x == 0 && t == 0) {
        g_idx64 = (src_words[1] == 0u && src_words[3] == 0u &&
                   src_words[5] == 0u && src_words[7] == 0u) ? 1 : 0;
    }

    // Stage W_fc (coalesced)
    #pragma unroll
    for (int i = 0; i < 16; i++) sW[i * 256 + t] = Wfc[i * 256 + t];

    // Stage h tile transposed: 2 threads per node (halves of the k range)
    {
        const int local = t & 127;
        const int half  = t >> 7;
        const int n     = nb0 + local;
        #pragma unroll
        for (int k4 = 0; k4 < 8; k4++) {
            const int kk = half * 8 + k4;
            float4 v = make_float4(0.f, 0.f, 0.f, 0.f);
            if (n < NN) v = reinterpret_cast<const float4*>(h)[n * 16 + kk];
            sT[(kk * 4 + 0) * 128 + local] = v.x;
            sT[(kk * 4 + 1) * 128 + local] = v.y;
            sT[(kk * 4 + 2) * 128 + local] = v.z;
            sT[(kk * 4 + 3) * 128 + local] = v.w;
        }
    }
    __syncthreads();

    const int g    = t >> 2;   // group of 2 nodes
    const int head = t & 3;

    const float2* sT2 = reinterpret_cast<const float2*>(sT);
    const float4* sW4 = reinterpret_cast<const float4*>(sW);

    float acc[2][16];

    // ---------------- Phase 1: feat = h @ W_fc ----------------
    #pragma unroll
    for (int i = 0; i < 2; i++)
        #pragma unroll
        for (int j = 0; j < 16; j++) acc[i][j] = 0.f;

    #pragma unroll 8
    for (int k = 0; k < 64; k++) {
        const float2 hv = sT2[k * 64 + g];
        #pragma unroll
        for (int jq = 0; jq < 4; jq++) {
            const float4 w = sW4[k * 16 + head * 4 + jq];
            acc[0][jq * 4 + 0] += hv.x * w.x;
            acc[0][jq * 4 + 1] += hv.x * w.y;
            acc[0][jq * 4 + 2] += hv.x * w.z;
            acc[0][jq * 4 + 3] += hv.x * w.w;
            acc[1][jq * 4 + 0] += hv.y * w.x;
            acc[1][jq * 4 + 1] += hv.y * w.y;
            acc[1][jq * 4 + 2] += hv.y * w.z;
            acc[1][jq * 4 + 3] += hv.y * w.w;
        }
    }

    // Epilogue 1: write feat, el, er
    {
        float alr[16], arr[16];
        #pragma unroll
        for (int j = 0; j < 16; j++) {
            alr[j] = __ldg(&al[head * 16 + j]);
            arr[j] = __ldg(&ar[head * 16 + j]);
        }
        #pragma unroll
        for (int i = 0; i < 2; i++) {
            const int n = nb0 + g * 2 + i;
            if (n < NN) {
                float elv = 0.f, erv = 0.f;
                #pragma unroll
                for (int j = 0; j < 16; j++) {
                    elv += acc[i][j] * alr[j];
                    erv += acc[i][j] * arr[j];
                }
                float4* fp = reinterpret_cast<float4*>(&g_feat[n * 64 + head * 16]);
                #pragma unroll
                for (int jq = 0; jq < 4; jq++)
                    fp[jq] = make_float4(acc[i][jq * 4 + 0], acc[i][jq * 4 + 1],
                                         acc[i][jq * 4 + 2], acc[i][jq * 4 + 3]);
                g_el[n * 4 + head] = elv;
                g_er[n * 4 + head] = erv;
            }
        }
    }

    __syncthreads();
    #pragma unroll
    for (int i = 0; i < 16; i++) sW[i * 256 + t] = Wres[i * 256 + t];
    __syncthreads();

    // ---------------- Phase 2: resval = h @ W_res ----------------
    #pragma unroll
    for (int i = 0; i < 2; i++)
        #pragma unroll
        for (int j = 0; j < 16; j++) acc[i][j] = 0.f;

    #pragma unroll 8
    for (int k = 0; k < 64; k++) {
        const float2 hv = sT2[k * 64 + g];
        #pragma unroll
        for (int jq = 0; jq < 4; jq++) {
            const float4 w = sW4[k * 16 + head * 4 + jq];
            acc[0][jq * 4 + 0] += hv.x * w.x;
            acc[0][jq * 4 + 1] += hv.x * w.y;
            acc[0][jq * 4 + 2] += hv.x * w.z;
            acc[0][jq * 4 + 3] += hv.x * w.w;
            acc[1][jq * 4 + 0] += hv.y * w.x;
            acc[1][jq * 4 + 1] += hv.y * w.y;
            acc[1][jq * 4 + 2] += hv.y * w.z;
            acc[1][jq * 4 + 3] += hv.y * w.w;
        }
    }

    #pragma unroll
    for (int i = 0; i < 2; i++) {
        const int n = nb0 + g * 2 + i;
        if (n < NN) {
            float4* op = reinterpret_cast<float4*>(&out[n * 64 + head * 16]);
            #pragma unroll
            for (int jq = 0; jq < 4; jq++)
                op[jq] = make_float4(acc[i][jq * 4 + 0], acc[i][jq * 4 + 1],
                                     acc[i][jq * 4 + 2], acc[i][jq * 4 + 3]);
        }
    }
}

// ---------------------------------------------------------------------------
// Edge kernel: 4 threads (one quad) per edge. Head-softmax via quad shuffles.
// COALESCED vector phase: for step j, lane q handles chunk c=4j+q (16 B), so
// the quad covers one contiguous 64 B span of feat/out -> minimum wavefronts.
// Chunk c belongs to head j; its weight a_j is fetched via quad shuffle.
// ---------------------------------------------------------------------------
__global__ __launch_bounds__(256)
void edge_kernel(const void* __restrict__ src_raw,
                 const void* __restrict__ dst_raw,
                 float* __restrict__ out)
{
    const int t = blockIdx.x * 256 + threadIdx.x;
    const int e = t >> 2;
    if (e >= EE) return;
    const int q    = t & 3;          // quad lane = head for the score phase
    const int lane = threadIdx.x & 31;

    int s, d;
    if (g_idx64) {
        s = (int)__ldg(&((const long long*)src_raw)[e]);
        d = (int)__ldg(&((const long long*)dst_raw)[e]);
    } else {
        s = __ldg(&((const int*)src_raw)[e]);
        d = __ldg(&((const int*)dst_raw)[e]);
    }

    float x = __ldg(&g_el[s * 4 + q]) + __ldg(&g_er[d * 4 + q]);
    x = (x > 0.f) ? x : 0.2f * x;                       // leaky relu

    // softmax over the 4 heads (lanes of this quad)
    float m = x;
    m = fmaxf(m, __shfl_xor_sync(0xFFFFFFFFu, m, 1));
    m = fmaxf(m, __shfl_xor_sync(0xFFFFFFFFu, m, 2));
    const float p = __expf(x - m);
    float ssum = p;
    ssum += __shfl_xor_sync(0xFFFFFFFFu, ssum, 1);
    ssum += __shfl_xor_sync(0xFFFFFFFFu, ssum, 2);
    const float a = p / ssum;        // this lane's head weight

    const float4* f4 = reinterpret_cast<const float4*>(g_feat) + s * 16;
    float*        o  = out + d * 64;
    const int     qb = lane & ~3;    // first lane of this quad

    #pragma unroll
    for (int j = 0; j < 4; j++) {
        const float aj = __shfl_sync(0xFFFFFFFFu, a, qb + j);
        const float4 v = __ldg(&f4[j * 4 + q]);
        asm volatile("red.global.add.v4.f32 [%0], {%1,%2,%3,%4};"
                     :: "l"(o + (j * 4 + q) * 4),
                        "f"(v.x * aj), "f"(v.y * aj), "f"(v.z * aj), "f"(v.w * aj)
                     : "memory");
    }
}

// ---------------------------------------------------------------------------
extern "C" void kernel_launch(void* const* d_in, const int* in_sizes, int n_in,
                              void* d_out, int out_size)
{
    const float* h    = (const float*)d_in[0];
    const void*  src  = d_in[1];
    const void*  dst  = d_in[2];
    const float* Wfc  = (const float*)d_in[3];
    const float* al   = (const float*)d_in[4];
    const float* ar   = (const float*)d_in[5];
    const float* Wres = (const float*)d_in[6];
    float* out = (float*)d_out;

    const int smem_bytes = (4096 + 64 * 128) * sizeof(float);  // 48 KB
    cudaFuncSetAttribute(node_kernel, cudaFuncAttributeMaxDynamicSharedMemorySize,
                         smem_bytes);

    const int node_blocks = (NN + NPB - 1) / NPB;    // 391
    node_kernel<<<node_blocks, 256, smem_bytes>>>(h, Wfc, Wres, al, ar, out,
                                                  (const unsigned*)src);

    const int edge_blocks = (EE * 4) / 256;          // 12500 (exact)
    edge_kernel<<<edge_blocks, 256>>>(src, dst, out);
}

// round 6
// speedup vs baseline: 1.2437x; 1.1796x over previous
#include <cuda_runtime.h>
#include <cuda_fp16.h>

#define NN 50000
#define EE 800000

// Scratch (allocation-free rule: __device__ globals)
__device__ __half g_feat[NN * 64];   // fp16 feat: 128 B / node record
__device__ float  g_el[NN * 4];
__device__ float  g_er[NN * 4];
__device__ int    g_idx64;           // 1 if src/dst are int64, 0 if int32

// ---------------------------------------------------------------------------
// Node kernel: feat = h@W_fc (stored fp16), el/er head-dots, out = h@W_res.
// Block = 256 threads = 64 groups x 4 heads; each group handles 4 nodes.
// SMEM: sW[64*64] (16 KB) + sT[64*256] transposed h tile (64 KB) -> occ 2.
// Block 0 / thread 0 probes index dtype (int32 vs int64): node ids < 2^31,
// so int64 encoding has zero high words at odd 32-bit slots.
// ---------------------------------------------------------------------------
__global__ __launch_bounds__(256, 2)
void node_kernel(const float* __restrict__ h,
                 const float* __restrict__ Wfc,
                 const float* __restrict__ Wres,
                 const float* __restrict__ al,
                 const float* __restrict__ ar,
                 float* __restrict__ out,
                 const unsigned* __restrict__ src_words)
{
    extern __shared__ float smem[];
    float* sW = smem;          // 4096 floats (16 KB)
    float* sT = smem + 4096;   // 64 x 256 floats (64 KB), sT[k*256 + local]

    const int t   = threadIdx.x;
    const int nb0 = blockIdx.x * 256;

    if (blockIdx.x == 0 && t == 0) {
        g_idx64 = (src_words[1] == 0u && src_words[3] == 0u &&
                   src_words[5] == 0u && src_words[7] == 0u) ? 1 : 0;
    }

    // Stage W_fc (coalesced)
    #pragma unroll
    for (int i = 0; i < 16; i++) sW[i * 256 + t] = Wfc[i * 256 + t];

    // Stage h tile transposed: thread t owns node nb0+t
    {
        const int n = nb0 + t;
        #pragma unroll
        for (int k4 = 0; k4 < 16; k4++) {
            float4 v = make_float4(0.f, 0.f, 0.f, 0.f);
            if (n < NN) v = reinterpret_cast<const float4*>(h)[n * 16 + k4];
            sT[(k4 * 4 + 0) * 256 + t] = v.x;
            sT[(k4 * 4 + 1) * 256 + t] = v.y;
            sT[(k4 * 4 + 2) * 256 + t] = v.z;
            sT[(k4 * 4 + 3) * 256 + t] = v.w;
        }
    }
    __syncthreads();

    const int g    = t >> 2;   // group (4 nodes)
    const int head = t & 3;    // output column block = head*16 .. head*16+15

    const float4* sT4 = reinterpret_cast<const float4*>(sT);
    const float4* sW4 = reinterpret_cast<const float4*>(sW);

    float acc[4][16];

    // ---------------- Phase 1: feat = h @ W_fc ----------------
    #pragma unroll
    for (int i = 0; i < 4; i++)
        #pragma unroll
        for (int j = 0; j < 16; j++) acc[i][j] = 0.f;

    #pragma unroll 4
    for (int k = 0; k < 64; k++) {
        float4 hv = sT4[k * 64 + g];          // 4 nodes' h[k] (broadcast per quad)
        float hvv[4] = {hv.x, hv.y, hv.z, hv.w};
        #pragma unroll
        for (int jq = 0; jq < 4; jq++) {
            float4 w = sW4[k * 16 + head * 4 + jq];
            #pragma unroll
            for (int i = 0; i < 4; i++) {
                acc[i][jq * 4 + 0] += hvv[i] * w.x;
                acc[i][jq * 4 + 1] += hvv[i] * w.y;
                acc[i][jq * 4 + 2] += hvv[i] * w.z;
                acc[i][jq * 4 + 3] += hvv[i] * w.w;
            }
        }
    }

    // Epilogue 1: write feat (fp16), el, er
    {
        float alr[16], arr[16];
        #pragma unroll
        for (int j = 0; j < 16; j++) {
            alr[j] = __ldg(&al[head * 16 + j]);
            arr[j] = __ldg(&ar[head * 16 + j]);
        }
        #pragma unroll
        for (int i = 0; i < 4; i++) {
            const int n = nb0 + g * 4 + i;
            if (n < NN) {
                float elv = 0.f, erv = 0.f;
                #pragma unroll
                for (int j = 0; j < 16; j++) {
                    elv += acc[i][j] * alr[j];
                    erv += acc[i][j] * arr[j];
                }
                __half2 hh[8];
                #pragma unroll
                for (int j2 = 0; j2 < 8; j2++)
                    hh[j2] = __floats2half2_rn(acc[i][j2 * 2], acc[i][j2 * 2 + 1]);
                uint4* fp = reinterpret_cast<uint4*>(&g_feat[n * 64 + head * 16]);
                fp[0] = *reinterpret_cast<uint4*>(&hh[0]);
                fp[1] = *reinterpret_cast<uint4*>(&hh[4]);
                g_el[n * 4 + head] = elv;
                g_er[n * 4 + head] = erv;
            }
        }
    }

    __syncthreads();
    // Stage W_res
    #pragma unroll
    for (int i = 0; i < 16; i++) sW[i * 256 + t] = Wres[i * 256 + t];
    __syncthreads();

    // ---------------- Phase 2: resval = h @ W_res ----------------
    #pragma unroll
    for (int i = 0; i < 4; i++)
        #pragma unroll
        for (int j = 0; j < 16; j++) acc[i][j] = 0.f;

    #pragma unroll 4
    for (int k = 0; k < 64; k++) {
        float4 hv = sT4[k * 64 + g];
        float hvv[4] = {hv.x, hv.y, hv.z, hv.w};
        #pragma unroll
        for (int jq = 0; jq < 4; jq++) {
            float4 w = sW4[k * 16 + head * 4 + jq];
            #pragma unroll
            for (int i = 0; i < 4; i++) {
                acc[i][jq * 4 + 0] += hvv[i] * w.x;
                acc[i][jq * 4 + 1] += hvv[i] * w.y;
                acc[i][jq * 4 + 2] += hvv[i] * w.z;
                acc[i][jq * 4 + 3] += hvv[i] * w.w;
            }
        }
    }

    #pragma unroll
    for (int i = 0; i < 4; i++) {
        const int n = nb0 + g * 4 + i;
        if (n < NN) {
            float4* op = reinterpret_cast<float4*>(&out[n * 64 + head * 16]);
            #pragma unroll
            for (int jq = 0; jq < 4; jq++)
                op[jq] = make_float4(acc[i][jq * 4 + 0], acc[i][jq * 4 + 1],
                                     acc[i][jq * 4 + 2], acc[i][jq * 4 + 3]);
        }
    }
}

// ---------------------------------------------------------------------------
// Edge kernel: 4 threads (one quad) per edge. Head-softmax via quad shuffles.
// Vector phase: step j, lane q handles chunk c=4j+q (4 fp16 = 8 B), so the
// quad covers one contiguous 32 B sector of the fp16 feat record; RED output
// spans contiguous 64 B per step. Chunk c belongs to head j (weight via shfl).
// ---------------------------------------------------------------------------
__global__ __launch_bounds__(256)
void edge_kernel(const void* __restrict__ src_raw,
                 const void* __restrict__ dst_raw,
                 float* __restrict__ out)
{
    const int t = blockIdx.x * 256 + threadIdx.x;
    const int e = t >> 2;
    if (e >= EE) return;
    const int q    = t & 3;          // quad lane = head for the score phase
    const int lane = threadIdx.x & 31;

    int s, d;
    if (g_idx64) {
        s = (int)__ldg(&((const long long*)src_raw)[e]);
        d = (int)__ldg(&((const long long*)dst_raw)[e]);
    } else {
        s = __ldg(&((const int*)src_raw)[e]);
        d = __ldg(&((const int*)dst_raw)[e]);
    }

    float x = __ldg(&g_el[s * 4 + q]) + __ldg(&g_er[d * 4 + q]);
    x = (x > 0.f) ? x : 0.2f * x;                       // leaky relu

    // softmax over the 4 heads (lanes of this quad)
    float m = x;
    m = fmaxf(m, __shfl_xor_sync(0xFFFFFFFFu, m, 1));
    m = fmaxf(m, __shfl_xor_sync(0xFFFFFFFFu, m, 2));
    const float p = __expf(x - m);
    float ssum = p;
    ssum += __shfl_xor_sync(0xFFFFFFFFu, ssum, 1);
    ssum += __shfl_xor_sync(0xFFFFFFFFu, ssum, 2);
    const float a = p / ssum;        // this lane's head weight

    const uint2* fh = reinterpret_cast<const uint2*>(g_feat + s * 64);  // 8 B chunks
    float*       o  = out + d * 64;
    const int    qb = lane & ~3;     // first lane of this quad

    #pragma unroll
    for (int j = 0; j < 4; j++) {
        const float aj = __shfl_sync(0xFFFFFFFFu, a, qb + j);
        const int   c  = j * 4 + q;
        const uint2 u  = __ldg(&fh[c]);
        const __half2 h0 = *reinterpret_cast<const __half2*>(&u.x);
        const __half2 h1 = *reinterpret_cast<const __half2*>(&u.y);
        const float2 f0 = __half22float2(h0);
        const float2 f1 = __half22float2(h1);
        asm volatile("red.global.add.v4.f32 [%0], {%1,%2,%3,%4};"
                     :: "l"(o + c * 4),
                        "f"(f0.x * aj), "f"(f0.y * aj), "f"(f1.x * aj), "f"(f1.y * aj)
                     : "memory");
    }
}

// ---------------------------------------------------------------------------
extern "C" void kernel_launch(void* const* d_in, const int* in_sizes, int n_in,
                              void* d_out, int out_size)
{
    const float* h    = (const float*)d_in[0];
    const void*  src  = d_in[1];
    const void*  dst  = d_in[2];
    const float* Wfc  = (const float*)d_in[3];
    const float* al   = (const float*)d_in[4];
    const float* ar   = (const float*)d_in[5];
    const float* Wres = (const float*)d_in[6];
    float* out = (float*)d_out;

    const int smem_bytes = (4096 + 64 * 256) * sizeof(float);  // 80 KB
    cudaFuncSetAttribute(node_kernel, cudaFuncAttributeMaxDynamicSharedMemorySize,
                         smem_bytes);

    const int node_blocks = (NN + 255) / 256;        // 196
    node_kernel<<<node_blocks, 256, smem_bytes>>>(h, Wfc, Wres, al, ar, out,
                                                  (const unsigned*)src);

    const int edge_blocks = (EE * 4) / 256;          // 12500 (exact)
    edge_kernel<<<edge_blocks, 256>>>(src, dst, out);
}

// round 7
// speedup vs baseline: 1.3152x; 1.0575x over previous
#include <cuda_runtime.h>
#include <cuda_fp16.h>

#define NN 50000
#define EE 800000
#define NPB 128   // nodes per block for the GEMM kernels

// Scratch (allocation-free rule: __device__ globals)
__device__ __half g_feat[NN * 64];   // fp16 feat: 128 B / node record
__device__ float  g_el[NN * 4];
__device__ float  g_er[NN * 4];
__device__ int    g_idx64;           // 1 if src/dst are int64, 0 if int32

// ---------------------------------------------------------------------------
// feat kernel: feat = h@W_fc (stored fp16), el/er head-dots.
// 128 threads = 32 groups x 4 heads; each group handles 4 nodes (128/block).
// SMEM: sW[64*64] (16 KB) + sT[64*128] transposed h tile (32 KB) -> occ 4,
// grid 391 fits in ONE wave (592 concurrent slots).
// Block 0 / thread 0 probes index dtype (int32 vs int64): node ids < 2^31,
// so int64 encoding has zero high words at odd 32-bit slots.
// ---------------------------------------------------------------------------
__global__ __launch_bounds__(128, 4)
void feat_kernel(const float* __restrict__ h,
                 const float* __restrict__ Wfc,
                 const float* __restrict__ al,
                 const float* __restrict__ ar,
                 const unsigned* __restrict__ src_words)
{
    extern __shared__ float smem[];
    float* sW = smem;          // 4096 floats (16 KB)
    float* sT = smem + 4096;   // 64 x 128 floats (32 KB), sT[k*128 + local]

    const int t   = threadIdx.x;
    const int nb0 = blockIdx.x * NPB;

    if (blockIdx.x == 0 && t == 0) {
        g_idx64 = (src_words[1] == 0u && src_words[3] == 0u &&
                   src_words[5] == 0u && src_words[7] == 0u) ? 1 : 0;
    }

    // Stage W_fc (coalesced): 4096 floats over 128 threads
    #pragma unroll
    for (int i = 0; i < 32; i++) sW[i * 128 + t] = Wfc[i * 128 + t];

    // Stage h tile transposed: thread t owns node nb0+t
    {
        const int n = nb0 + t;
        #pragma unroll
        for (int k4 = 0; k4 < 16; k4++) {
            float4 v = make_float4(0.f, 0.f, 0.f, 0.f);
            if (n < NN) v = reinterpret_cast<const float4*>(h)[n * 16 + k4];
            sT[(k4 * 4 + 0) * 128 + t] = v.x;
            sT[(k4 * 4 + 1) * 128 + t] = v.y;
            sT[(k4 * 4 + 2) * 128 + t] = v.z;
            sT[(k4 * 4 + 3) * 128 + t] = v.w;
        }
    }
    __syncthreads();

    const int g    = t >> 2;   // group (4 nodes), 0..31
    const int head = t & 3;

    const float4* sT4 = reinterpret_cast<const float4*>(sT);
    const float4* sW4 = reinterpret_cast<const float4*>(sW);

    float acc[4][16];
    #pragma unroll
    for (int i = 0; i < 4; i++)
        #pragma unroll
        for (int j = 0; j < 16; j++) acc[i][j] = 0.f;

    #pragma unroll 4
    for (int k = 0; k < 64; k++) {
        float4 hv = sT4[k * 32 + g];          // 4 nodes' h[k]
        float hvv[4] = {hv.x, hv.y, hv.z, hv.w};
        #pragma unroll
        for (int jq = 0; jq < 4; jq++) {
            float4 w = sW4[k * 16 + head * 4 + jq];
            #pragma unroll
            for (int i = 0; i < 4; i++) {
                acc[i][jq * 4 + 0] += hvv[i] * w.x;
                acc[i][jq * 4 + 1] += hvv[i] * w.y;
                acc[i][jq * 4 + 2] += hvv[i] * w.z;
                acc[i][jq * 4 + 3] += hvv[i] * w.w;
            }
        }
    }

    // Epilogue: feat (fp16), el, er
    float alr[16], arr[16];
    #pragma unroll
    for (int j = 0; j < 16; j++) {
        alr[j] = __ldg(&al[head * 16 + j]);
        arr[j] = __ldg(&ar[head * 16 + j]);
    }
    #pragma unroll
    for (int i = 0; i < 4; i++) {
        const int n = nb0 + g * 4 + i;
        if (n < NN) {
            float elv = 0.f, erv = 0.f;
            #pragma unroll
            for (int j = 0; j < 16; j++) {
                elv += acc[i][j] * alr[j];
                erv += acc[i][j] * arr[j];
            }
            __half2 hh[8];
            #pragma unroll
            for (int j2 = 0; j2 < 8; j2++)
                hh[j2] = __floats2half2_rn(acc[i][j2 * 2], acc[i][j2 * 2 + 1]);
            uint4* fp = reinterpret_cast<uint4*>(&g_feat[n * 64 + head * 16]);
            fp[0] = *reinterpret_cast<uint4*>(&hh[0]);
            fp[1] = *reinterpret_cast<uint4*>(&hh[4]);
            g_el[n * 4 + head] = elv;
            g_er[n * 4 + head] = erv;
        }
    }
}

// ---------------------------------------------------------------------------
// resval kernel: out = h @ W_res. Same tiling as feat_kernel. Runs on a
// forked stream, concurrent with feat_kernel; edge_kernel joins after both.
// ---------------------------------------------------------------------------
__global__ __launch_bounds__(128, 4)
void resval_kernel(const float* __restrict__ h,
                   const float* __restrict__ Wres,
                   float* __restrict__ out)
{
    extern __shared__ float smem[];
    float* sW = smem;
    float* sT = smem + 4096;

    const int t   = threadIdx.x;
    const int nb0 = blockIdx.x * NPB;

    #pragma unroll
    for (int i = 0; i < 32; i++) sW[i * 128 + t] = Wres[i * 128 + t];

    {
        const int n = nb0 + t;
        #pragma unroll
        for (int k4 = 0; k4 < 16; k4++) {
            float4 v = make_float4(0.f, 0.f, 0.f, 0.f);
            if (n < NN) v = reinterpret_cast<const float4*>(h)[n * 16 + k4];
            sT[(k4 * 4 + 0) * 128 + t] = v.x;
            sT[(k4 * 4 + 1) * 128 + t] = v.y;
            sT[(k4 * 4 + 2) * 128 + t] = v.z;
            sT[(k4 * 4 + 3) * 128 + t] = v.w;
        }
    }
    __syncthreads();

    const int g    = t >> 2;
    const int head = t & 3;

    const float4* sT4 = reinterpret_cast<const float4*>(sT);
    const float4* sW4 = reinterpret_cast<const float4*>(sW);

    float acc[4][16];
    #pragma unroll
    for (int i = 0; i < 4; i++)
        #pragma unroll
        for (int j = 0; j < 16; j++) acc[i][j] = 0.f;

    #pragma unroll 4
    for (int k = 0; k < 64; k++) {
        float4 hv = sT4[k * 32 + g];
        float hvv[4] = {hv.x, hv.y, hv.z, hv.w};
        #pragma unroll
        for (int jq = 0; jq < 4; jq++) {
            float4 w = sW4[k * 16 + head * 4 + jq];
            #pragma unroll
            for (int i = 0; i < 4; i++) {
                acc[i][jq * 4 + 0] += hvv[i] * w.x;
                acc[i][jq * 4 + 1] += hvv[i] * w.y;
                acc[i][jq * 4 + 2] += hvv[i] * w.z;
                acc[i][jq * 4 + 3] += hvv[i] * w.w;
            }
        }
    }

    #pragma unroll
    for (int i = 0; i < 4; i++) {
        const int n = nb0 + g * 4 + i;
        if (n < NN) {
            float4* op = reinterpret_cast<float4*>(&out[n * 64 + head * 16]);
            #pragma unroll
            for (int jq = 0; jq < 4; jq++)
                op[jq] = make_float4(acc[i][jq * 4 + 0], acc[i][jq * 4 + 1],
                                     acc[i][jq * 4 + 2], acc[i][jq * 4 + 3]);
        }
    }
}

// ---------------------------------------------------------------------------
// Edge kernel: 4 threads (one quad) per edge. Head-softmax via quad shuffles.
// fp16 feat gather (quad covers one 32 B sector per step); fp32 vector RED
// scatter (quad covers contiguous 64 B per step). At the L1-wavefront floor.
// ---------------------------------------------------------------------------
__global__ __launch_bounds__(256)
void edge_kernel(const void* __restrict__ src_raw,
                 const void* __restrict__ dst_raw,
                 float* __restrict__ out)
{
    const int t = blockIdx.x * 256 + threadIdx.x;
    const int e = t >> 2;
    if (e >= EE) return;
    const int q    = t & 3;
    const int lane = threadIdx.x & 31;

    int s, d;
    if (g_idx64) {
        s = (int)__ldg(&((const long long*)src_raw)[e]);
        d = (int)__ldg(&((const long long*)dst_raw)[e]);
    } else {
        s = __ldg(&((const int*)src_raw)[e]);
        d = __ldg(&((const int*)dst_raw)[e]);
    }

    float x = __ldg(&g_el[s * 4 + q]) + __ldg(&g_er[d * 4 + q]);
    x = (x > 0.f) ? x : 0.2f * x;                       // leaky relu

    float m = x;
    m = fmaxf(m, __shfl_xor_sync(0xFFFFFFFFu, m, 1));
    m = fmaxf(m, __shfl_xor_sync(0xFFFFFFFFu, m, 2));
    const float p = __expf(x - m);
    float ssum = p;
    ssum += __shfl_xor_sync(0xFFFFFFFFu, ssum, 1);
    ssum += __shfl_xor_sync(0xFFFFFFFFu, ssum, 2);
    const float a = p / ssum;

    const uint2* fh = reinterpret_cast<const uint2*>(g_feat + s * 64);
    float*       o  = out + d * 64;
    const int    qb = lane & ~3;

    #pragma unroll
    for (int j = 0; j < 4; j++) {
        const float aj = __shfl_sync(0xFFFFFFFFu, a, qb + j);
        const int   c  = j * 4 + q;
        const uint2 u  = __ldg(&fh[c]);
        const __half2 h0 = *reinterpret_cast<const __half2*>(&u.x);
        const __half2 h1 = *reinterpret_cast<const __half2*>(&u.y);
        const float2 f0 = __half22float2(h0);
        const float2 f1 = __half22float2(h1);
        asm volatile("red.global.add.v4.f32 [%0], {%1,%2,%3,%4};"
                     :: "l"(o + c * 4),
                        "f"(f0.x * aj), "f"(f0.y * aj), "f"(f1.x * aj), "f"(f1.y * aj)
                     : "memory");
    }
}

// ---------------------------------------------------------------------------
extern "C" void kernel_launch(void* const* d_in, const int* in_sizes, int n_in,
                              void* d_out, int out_size)
{
    const float* h    = (const float*)d_in[0];
    const void*  src  = d_in[1];
    const void*  dst  = d_in[2];
    const float* Wfc  = (const float*)d_in[3];
    const float* al   = (const float*)d_in[4];
    const float* ar   = (const float*)d_in[5];
    const float* Wres = (const float*)d_in[6];
    float* out = (float*)d_out;

    // One-time host-side resources (no device memory involved).
    static bool         s_init = false;
    static cudaStream_t s2;
    static cudaEvent_t  evFork, evJoin;
    if (!s_init) {
        cudaStreamCreateWithFlags(&s2, cudaStreamNonBlocking);
        cudaEventCreateWithFlags(&evFork, cudaEventDisableTiming);
        cudaEventCreateWithFlags(&evJoin, cudaEventDisableTiming);
        cudaFuncSetAttribute(feat_kernel,
                             cudaFuncAttributeMaxDynamicSharedMemorySize,
                             (4096 + 64 * NPB) * (int)sizeof(float));
        cudaFuncSetAttribute(resval_kernel,
                             cudaFuncAttributeMaxDynamicSharedMemorySize,
                             (4096 + 64 * NPB) * (int)sizeof(float));
        s_init = true;
    }

    const int smem_bytes  = (4096 + 64 * NPB) * sizeof(float);  // 48 KB
    const int node_blocks = (NN + NPB - 1) / NPB;               // 391

    // Fork: resval on s2 runs concurrently with feat on the main stream.
    cudaEventRecord(evFork, 0);
    cudaStreamWaitEvent(s2, evFork, 0);
    resval_kernel<<<node_blocks, 128, smem_bytes, s2>>>(h, Wres, out);
    cudaEventRecord(evJoin, s2);

    feat_kernel<<<node_blocks, 128, smem_bytes>>>(h, Wfc, al, ar,
                                                  (const unsigned*)src);

    // Join: edge RED-adds on top of resval's stores -> must wait for both.
    cudaStreamWaitEvent(0, evJoin, 0);

    const int edge_blocks = (EE * 4) / 256;          // 12500 (exact)
    edge_kernel<<<edge_blocks, 256>>>(src, dst, out);
}

// round 8
// speedup vs baseline: 1.3973x; 1.0625x over previous
#include <cuda_runtime.h>
#include <cuda_fp16.h>

#define NN 50000
#define EE 800000
#define NPB 128   // nodes per block for the GEMM kernels

// Scratch (allocation-free rule: __device__ globals)
__device__ __half g_feat[NN * 64];   // fp16 feat: 128 B / node record
__device__ float  g_el[NN * 4];
__device__ float  g_er[NN * 4];
__device__ int    g_idx64;           // 1 if src/dst are int64, 0 if int32

// ---------------------------------------------------------------------------
// Zero kernel: out = 0 (out is poisoned; both resval and edge RED-add onto it)
// ---------------------------------------------------------------------------
__global__ __launch_bounds__(256)
void zero_kernel(float4* __restrict__ out4)
{
    const int i = blockIdx.x * 256 + threadIdx.x;
    if (i < NN * 16) out4[i] = make_float4(0.f, 0.f, 0.f, 0.f);
}

// ---------------------------------------------------------------------------
// feat kernel: feat = h@W_fc (stored fp16), el/er head-dots.
// 128 threads = 32 groups x 4 heads; each group handles 4 nodes (128/block).
// SMEM: sW[64*64] (16 KB) + sT[64*128] transposed h tile (32 KB).
// Block 0 / thread 0 probes index dtype (int32 vs int64): node ids < 2^31,
// so int64 encoding has zero high words at odd 32-bit slots.
// ---------------------------------------------------------------------------
__global__ __launch_bounds__(128, 4)
void feat_kernel(const float* __restrict__ h,
                 const float* __restrict__ Wfc,
                 const float* __restrict__ al,
                 const float* __restrict__ ar,
                 const unsigned* __restrict__ src_words)
{
    extern __shared__ float smem[];
    float* sW = smem;          // 4096 floats (16 KB)
    float* sT = smem + 4096;   // 64 x 128 floats (32 KB), sT[k*128 + local]

    const int t   = threadIdx.x;
    const int nb0 = blockIdx.x * NPB;

    if (blockIdx.x == 0 && t == 0) {
        g_idx64 = (src_words[1] == 0u && src_words[3] == 0u &&
                   src_words[5] == 0u && src_words[7] == 0u) ? 1 : 0;
    }

    #pragma unroll
    for (int i = 0; i < 32; i++) sW[i * 128 + t] = Wfc[i * 128 + t];

    {
        const int n = nb0 + t;
        #pragma unroll
        for (int k4 = 0; k4 < 16; k4++) {
            float4 v = make_float4(0.f, 0.f, 0.f, 0.f);
            if (n < NN) v = reinterpret_cast<const float4*>(h)[n * 16 + k4];
            sT[(k4 * 4 + 0) * 128 + t] = v.x;
            sT[(k4 * 4 + 1) * 128 + t] = v.y;
            sT[(k4 * 4 + 2) * 128 + t] = v.z;
            sT[(k4 * 4 + 3) * 128 + t] = v.w;
        }
    }
    __syncthreads();

    const int g    = t >> 2;   // group (4 nodes), 0..31
    const int head = t & 3;

    const float4* sT4 = reinterpret_cast<const float4*>(sT);
    const float4* sW4 = reinterpret_cast<const float4*>(sW);

    float acc[4][16];
    #pragma unroll
    for (int i = 0; i < 4; i++)
        #pragma unroll
        for (int j = 0; j < 16; j++) acc[i][j] = 0.f;

    #pragma unroll 4
    for (int k = 0; k < 64; k++) {
        float4 hv = sT4[k * 32 + g];
        float hvv[4] = {hv.x, hv.y, hv.z, hv.w};
        #pragma unroll
        for (int jq = 0; jq < 4; jq++) {
            float4 w = sW4[k * 16 + head * 4 + jq];
            #pragma unroll
            for (int i = 0; i < 4; i++) {
                acc[i][jq * 4 + 0] += hvv[i] * w.x;
                acc[i][jq * 4 + 1] += hvv[i] * w.y;
                acc[i][jq * 4 + 2] += hvv[i] * w.z;
                acc[i][jq * 4 + 3] += hvv[i] * w.w;
            }
        }
    }

    float alr[16], arr[16];
    #pragma unroll
    for (int j = 0; j < 16; j++) {
        alr[j] = __ldg(&al[head * 16 + j]);
        arr[j] = __ldg(&ar[head * 16 + j]);
    }
    #pragma unroll
    for (int i = 0; i < 4; i++) {
        const int n = nb0 + g * 4 + i;
        if (n < NN) {
            float elv = 0.f, erv = 0.f;
            #pragma unroll
            for (int j = 0; j < 16; j++) {
                elv += acc[i][j] * alr[j];
                erv += acc[i][j] * arr[j];
            }
            __half2 hh[8];
            #pragma unroll
            for (int j2 = 0; j2 < 8; j2++)
                hh[j2] = __floats2half2_rn(acc[i][j2 * 2], acc[i][j2 * 2 + 1]);
            uint4* fp = reinterpret_cast<uint4*>(&g_feat[n * 64 + head * 16]);
            fp[0] = *reinterpret_cast<uint4*>(&hh[0]);
            fp[1] = *reinterpret_cast<uint4*>(&hh[4]);
            g_el[n * 4 + head] = elv;
            g_er[n * 4 + head] = erv;
        }
    }
}

// ---------------------------------------------------------------------------
// resval kernel: out += h @ W_res, scattered with red.add.v4 so it can run
// CONCURRENTLY with edge_kernel's RED accumulation (addition commutes).
// ---------------------------------------------------------------------------
__global__ __launch_bounds__(128, 4)
void resval_kernel(const float* __restrict__ h,
                   const float* __restrict__ Wres,
                   float* __restrict__ out)
{
    extern __shared__ float smem[];
    float* sW = smem;
    float* sT = smem + 4096;

    const int t   = threadIdx.x;
    const int nb0 = blockIdx.x * NPB;

    #pragma unroll
    for (int i = 0; i < 32; i++) sW[i * 128 + t] = Wres[i * 128 + t];

    {
        const int n = nb0 + t;
        #pragma unroll
        for (int k4 = 0; k4 < 16; k4++) {
            float4 v = make_float4(0.f, 0.f, 0.f, 0.f);
            if (n < NN) v = reinterpret_cast<const float4*>(h)[n * 16 + k4];
            sT[(k4 * 4 + 0) * 128 + t] = v.x;
            sT[(k4 * 4 + 1) * 128 + t] = v.y;
            sT[(k4 * 4 + 2) * 128 + t] = v.z;
            sT[(k4 * 4 + 3) * 128 + t] = v.w;
        }
    }
    __syncthreads();

    const int g    = t >> 2;
    const int head = t & 3;

    const float4* sT4 = reinterpret_cast<const float4*>(sT);
    const float4* sW4 = reinterpret_cast<const float4*>(sW);

    float acc[4][16];
    #pragma unroll
    for (int i = 0; i < 4; i++)
        #pragma unroll
        for (int j = 0; j < 16; j++) acc[i][j] = 0.f;

    #pragma unroll 4
    for (int k = 0; k < 64; k++) {
        float4 hv = sT4[k * 32 + g];
        float hvv[4] = {hv.x, hv.y, hv.z, hv.w};
        #pragma unroll
        for (int jq = 0; jq < 4; jq++) {
            float4 w = sW4[k * 16 + head * 4 + jq];
            #pragma unroll
            for (int i = 0; i < 4; i++) {
                acc[i][jq * 4 + 0] += hvv[i] * w.x;
                acc[i][jq * 4 + 1] += hvv[i] * w.y;
                acc[i][jq * 4 + 2] += hvv[i] * w.z;
                acc[i][jq * 4 + 3] += hvv[i] * w.w;
            }
        }
    }

    #pragma unroll
    for (int i = 0; i < 4; i++) {
        const int n = nb0 + g * 4 + i;
        if (n < NN) {
            float* op = &out[n * 64 + head * 16];
            #pragma unroll
            for (int jq = 0; jq < 4; jq++) {
                asm volatile("red.global.add.v4.f32 [%0], {%1,%2,%3,%4};"
                             :: "l"(op + jq * 4),
                                "f"(acc[i][jq * 4 + 0]), "f"(acc[i][jq * 4 + 1]),
                                "f"(acc[i][jq * 4 + 2]), "f"(acc[i][jq * 4 + 3])
                             : "memory");
            }
        }
    }
}

// ---------------------------------------------------------------------------
// Edge kernel: 4 threads (one quad) per edge. Head-softmax via quad shuffles.
// fp16 feat gather (quad covers one 32 B sector per step); fp32 vector RED
// scatter (quad covers contiguous 64 B per step). At the L1-wavefront floor.
// ---------------------------------------------------------------------------
__global__ __launch_bounds__(256)
void edge_kernel(const void* __restrict__ src_raw,
                 const void* __restrict__ dst_raw,
                 float* __restrict__ out)
{
    const int t = blockIdx.x * 256 + threadIdx.x;
    const int e = t >> 2;
    if (e >= EE) return;
    const int q    = t & 3;
    const int lane = threadIdx.x & 31;

    int s, d;
    if (g_idx64) {
        s = (int)__ldg(&((const long long*)src_raw)[e]);
        d = (int)__ldg(&((const long long*)dst_raw)[e]);
    } else {
        s = __ldg(&((const int*)src_raw)[e]);
        d = __ldg(&((const int*)dst_raw)[e]);
    }

    float x = __ldg(&g_el[s * 4 + q]) + __ldg(&g_er[d * 4 + q]);
    x = (x > 0.f) ? x : 0.2f * x;                       // leaky relu

    float m = x;
    m = fmaxf(m, __shfl_xor_sync(0xFFFFFFFFu, m, 1));
    m = fmaxf(m, __shfl_xor_sync(0xFFFFFFFFu, m, 2));
    const float p = __expf(x - m);
    float ssum = p;
    ssum += __shfl_xor_sync(0xFFFFFFFFu, ssum, 1);
    ssum += __shfl_xor_sync(0xFFFFFFFFu, ssum, 2);
    const float a = p / ssum;

    const uint2* fh = reinterpret_cast<const uint2*>(g_feat + s * 64);
    float*       o  = out + d * 64;
    const int    qb = lane & ~3;

    #pragma unroll
    for (int j = 0; j < 4; j++) {
        const float aj = __shfl_sync(0xFFFFFFFFu, a, qb + j);
        const int   c  = j * 4 + q;
        const uint2 u  = __ldg(&fh[c]);
        const __half2 h0 = *reinterpret_cast<const __half2*>(&u.x);
        const __half2 h1 = *reinterpret_cast<const __half2*>(&u.y);
        const float2 f0 = __half22float2(h0);
        const float2 f1 = __half22float2(h1);
        asm volatile("red.global.add.v4.f32 [%0], {%1,%2,%3,%4};"
                     :: "l"(o + c * 4),
                        "f"(f0.x * aj), "f"(f0.y * aj), "f"(f1.x * aj), "f"(f1.y * aj)
                     : "memory");
    }
}

// ---------------------------------------------------------------------------
// Schedule:
//   s2 : zero_out ──► resval (RED into out) ──────────────┐
//   s1 : feat ───────────────► [wait zero] edge ──────────┴► join
// resval (pure FMA) hides under edge (L1-bound); edge starts right after feat.
// ---------------------------------------------------------------------------
extern "C" void kernel_launch(void* const* d_in, const int* in_sizes, int n_in,
                              void* d_out, int out_size)
{
    const float* h    = (const float*)d_in[0];
    const void*  src  = d_in[1];
    const void*  dst  = d_in[2];
    const float* Wfc  = (const float*)d_in[3];
    const float* al   = (const float*)d_in[4];
    const float* ar   = (const float*)d_in[5];
    const float* Wres = (const float*)d_in[6];
    float* out = (float*)d_out;

    // One-time host-side resources (no device memory involved).
    static bool         s_init = false;
    static cudaStream_t s2;
    static cudaEvent_t  evFork, evZero, evJoin;
    if (!s_init) {
        cudaStreamCreateWithFlags(&s2, cudaStreamNonBlocking);
        cudaEventCreateWithFlags(&evFork, cudaEventDisableTiming);
        cudaEventCreateWithFlags(&evZero, cudaEventDisableTiming);
        cudaEventCreateWithFlags(&evJoin, cudaEventDisableTiming);
        cudaFuncSetAttribute(feat_kernel,
                             cudaFuncAttributeMaxDynamicSharedMemorySize,
                             (4096 + 64 * NPB) * (int)sizeof(float));
        cudaFuncSetAttribute(resval_kernel,
                             cudaFuncAttributeMaxDynamicSharedMemorySize,
                             (4096 + 64 * NPB) * (int)sizeof(float));
        s_init = true;
    }

    const int smem_bytes  = (4096 + 64 * NPB) * sizeof(float);  // 48 KB
    const int node_blocks = (NN + NPB - 1) / NPB;               // 391

    // Fork s2: zero out, then resval RED-adds into it.
    cudaEventRecord(evFork, 0);
    cudaStreamWaitEvent(s2, evFork, 0);
    zero_kernel<<<(NN * 16 + 255) / 256, 256, 0, s2>>>((float4*)out);
    cudaEventRecord(evZero, s2);
    resval_kernel<<<node_blocks, 128, smem_bytes, s2>>>(h, Wres, out);
    cudaEventRecord(evJoin, s2);

    // Main stream: feat, then edge (edge needs feat AND zeroed out).
    feat_kernel<<<node_blocks, 128, smem_bytes>>>(h, Wfc, al, ar,
                                                  (const unsigned*)src);
    cudaStreamWaitEvent(0, evZero, 0);

    const int edge_blocks = (EE * 4) / 256;          // 12500 (exact)
    edge_kernel<<<edge_blocks, 256>>>(src, dst, out);

    // Join: resval must also be complete before the result is read.
    cudaStreamWaitEvent(0, evJoin, 0);
}

// round 10
// speedup vs baseline: 1.5359x; 1.0992x over previous
#include <cuda_runtime.h>
#include <cuda_fp16.h>
#include <cstdint>

#define NN 50000
#define EE 800000
#define NPB 128   // nodes per block for the GEMM kernels
#define HS_H 72   // h-tile smem stride in halves (144 B: conflict-free ldmatrix)
#define WT_S 72   // transposed-W smem stride in halves

// Scratch (allocation-free rule: __device__ globals)
__device__ __half g_feat[NN * 64];   // fp16 feat: 128 B / node record
__device__ float  g_el[NN * 4];
__device__ float  g_er[NN * 4];
__device__ int    g_idx64;           // 1 if src/dst are int64, 0 if int32

__device__ __forceinline__ uint32_t smem_u32(const void* p)
{
    return (uint32_t)__cvta_generic_to_shared(p);
}

// ---------------------------------------------------------------------------
// Zero kernel: out = 0 (out is poisoned; both resval and edge RED-add onto it)
// ---------------------------------------------------------------------------
__global__ __launch_bounds__(256)
void zero_kernel(float4* __restrict__ out4)
{
    const int i = blockIdx.x * 256 + threadIdx.x;
    if (i < NN * 16) out4[i] = make_float4(0.f, 0.f, 0.f, 0.f);
}

// ---------------------------------------------------------------------------
// feat kernel (fp16 tensor cores, ldmatrix-fed): feat = h@W_fc (stored fp16),
// el/er head-dots from the fp32 accumulators.
// 128 threads = 4 warps; warp w owns rows w*32..w*32+31 x all 64 cols as
// 2 (M16) x 8 (N8) tiles, K=64 in 4 k16 steps.
// A fragments: ldmatrix.x4 from row-major fp16 h tile.
// B fragments: ldmatrix.x4 from TRANSPOSED W (Wt[n][k], k contiguous) -> two
// n-tiles (k-low/k-high each) per instruction.
// Block 0 / thread 0 probes index dtype (int32 vs int64): node ids < 2^31,
// so int64 encoding has zero high words at odd 32-bit slots.
// ---------------------------------------------------------------------------
__global__ __launch_bounds__(128)
void feat_kernel(const float* __restrict__ h,
                 const float* __restrict__ Wfc,
                 const float* __restrict__ al,
                 const float* __restrict__ ar,
                 const unsigned* __restrict__ src_words)
{
    extern __shared__ float smem[];
    __half* hs   = reinterpret_cast<__half*>(smem);           // [128][HS_H]
    __half* Wt   = hs + 128 * HS_H;                           // [64][WT_S]
    float*  al_s = reinterpret_cast<float*>(Wt + 64 * WT_S);  // 64 (4B-aligned)
    float*  ar_s = al_s + 64;                                 // 64

    const int t   = threadIdx.x;
    const int nb0 = blockIdx.x * NPB;

    if (blockIdx.x == 0 && t == 0) {
        g_idx64 = (src_words[1] == 0u && src_words[3] == 0u &&
                   src_words[5] == 0u && src_words[7] == 0u) ? 1 : 0;
    }

    // Stage al/ar
    if (t < 64)       al_s[t]      = al[t];
    else if (t < 128) ar_s[t - 64] = ar[t - 64];

    // Stage W transposed as fp16: Wt[n][k] = W[k][n]
    #pragma unroll
    for (int i = 0; i < 32; i++) {
        const int idx = i * 128 + t;
        const int k = idx >> 6, n = idx & 63;
        Wt[n * WT_S + k] = __float2half(Wfc[idx]);
    }

    // Stage h row t as fp16
    {
        const int n = nb0 + t;
        #pragma unroll
        for (int k4 = 0; k4 < 16; k4++) {
            float4 v = make_float4(0.f, 0.f, 0.f, 0.f);
            if (n < NN) v = reinterpret_cast<const float4*>(h)[n * 16 + k4];
            *reinterpret_cast<__half2*>(&hs[t * HS_H + k4 * 4 + 0]) =
                __floats2half2_rn(v.x, v.y);
            *reinterpret_cast<__half2*>(&hs[t * HS_H + k4 * 4 + 2]) =
                __floats2half2_rn(v.z, v.w);
        }
    }
    __syncthreads();

    const int w   = t >> 5;
    const int ln  = t & 31;
    const int gid = ln >> 2;   // groupID (row within tile)
    const int q   = ln & 3;    // threadID in group
    const int rbase = w * 32;

    // Per-lane ldmatrix address components
    const int arow_l = ln & 15;          // A: row within 16 (matrices 0/1 low, 2/3 high rows)
    const int akoff  = (ln >> 4) * 8;    // A: k-offset (matrices 0,1 -> 0; 2,3 -> 8)
    const int brow_l = ln & 7;           // B: row within its 8x8 matrix
    const int bj     = ln >> 3;          // B: matrix index 0..3
    const int bkoff  = (bj & 1) * 8;     // B: matrices 0,2 k-low; 1,3 k-high
    const int bnsel  = bj >> 1;          // B: matrices 0,1 -> n-tile nt; 2,3 -> nt+1

    const uint32_t hs_base = smem_u32(hs);
    const uint32_t wt_base = smem_u32(Wt);

    float acc[2][8][4];
    #pragma unroll
    for (int m = 0; m < 2; m++)
        #pragma unroll
        for (int nt = 0; nt < 8; nt++)
            #pragma unroll
            for (int c = 0; c < 4; c++) acc[m][nt][c] = 0.f;

    #pragma unroll
    for (int ks = 0; ks < 4; ks++) {
        const int k0 = ks * 16;

        uint32_t a[2][4];
        #pragma unroll
        for (int m = 0; m < 2; m++) {
            const uint32_t addr = hs_base +
                ((rbase + m * 16 + arow_l) * HS_H + k0 + akoff) * 2;
            asm volatile(
                "ldmatrix.sync.aligned.m8n8.x4.shared.b16 {%0,%1,%2,%3}, [%4];"
                : "=r"(a[m][0]), "=r"(a[m][1]), "=r"(a[m][2]), "=r"(a[m][3])
                : "r"(addr));
        }

        #pragma unroll
        for (int np = 0; np < 4; np++) {    // n-tile pair (2np, 2np+1)
            uint32_t b[4];
            const int nrow = (2 * np + bnsel) * 8 + brow_l;
            const uint32_t baddr = wt_base + (nrow * WT_S + k0 + bkoff) * 2;
            asm volatile(
                "ldmatrix.sync.aligned.m8n8.x4.shared.b16 {%0,%1,%2,%3}, [%4];"
                : "=r"(b[0]), "=r"(b[1]), "=r"(b[2]), "=r"(b[3])
                : "r"(baddr));
            #pragma unroll
            for (int hf = 0; hf < 2; hf++) {
                const int nt = 2 * np + hf;
                #pragma unroll
                for (int m = 0; m < 2; m++) {
                    asm volatile(
                        "mma.sync.aligned.m16n8k16.row.col.f32.f16.f16.f32 "
                        "{%0,%1,%2,%3},{%4,%5,%6,%7},{%8,%9},{%0,%1,%2,%3};"
                        : "+f"(acc[m][nt][0]), "+f"(acc[m][nt][1]),
                          "+f"(acc[m][nt][2]), "+f"(acc[m][nt][3])
                        : "r"(a[m][0]), "r"(a[m][1]), "r"(a[m][2]), "r"(a[m][3]),
                          "r"(b[hf * 2 + 0]), "r"(b[hf * 2 + 1]));
                }
            }
        }
    }

    // Epilogue: per lane rows (m, gid + 8*half); cols nt*8 + 2q, +1.
    #pragma unroll
    for (int m = 0; m < 2; m++) {
        #pragma unroll
        for (int half = 0; half < 2; half++) {
            const int n = nb0 + rbase + m * 16 + gid + half * 8;
            float e_l[4] = {0.f, 0.f, 0.f, 0.f};
            float e_r[4] = {0.f, 0.f, 0.f, 0.f};
            #pragma unroll
            for (int nt = 0; nt < 8; nt++) {
                const int hH  = nt >> 1;
                const int c16 = (nt & 1) * 8 + 2 * q;
                const float v0 = acc[m][nt][half * 2 + 0];
                const float v1 = acc[m][nt][half * 2 + 1];
                e_l[hH] += v0 * al_s[hH * 16 + c16] + v1 * al_s[hH * 16 + c16 + 1];
                e_r[hH] += v0 * ar_s[hH * 16 + c16] + v1 * ar_s[hH * 16 + c16 + 1];
            }
            // Quad reduce (lanes of a quad hold the same row)
            #pragma unroll
            for (int hH = 0; hH < 4; hH++) {
                e_l[hH] += __shfl_xor_sync(0xFFFFFFFFu, e_l[hH], 1);
                e_l[hH] += __shfl_xor_sync(0xFFFFFFFFu, e_l[hH], 2);
                e_r[hH] += __shfl_xor_sync(0xFFFFFFFFu, e_r[hH], 1);
                e_r[hH] += __shfl_xor_sync(0xFFFFFFFFu, e_r[hH], 2);
            }
            if (n < NN) {
                #pragma unroll
                for (int nt = 0; nt < 8; nt++) {
                    const __half2 hv = __floats2half2_rn(acc[m][nt][half * 2 + 0],
                                                         acc[m][nt][half * 2 + 1]);
                    *reinterpret_cast<__half2*>(&g_feat[n * 64 + nt * 8 + 2 * q]) = hv;
                }
                const float ev = (q == 0) ? e_l[0] : (q == 1) ? e_l[1]
                               : (q == 2) ? e_l[2] : e_l[3];
                const float rv = (q == 0) ? e_r[0] : (q == 1) ? e_r[1]
                               : (q == 2) ? e_r[2] : e_r[3];
                g_el[n * 4 + q] = ev;
                g_er[n * 4 + q] = rv;
            }
        }
    }
}

// ---------------------------------------------------------------------------
// resval kernel (fp32 FFMA, off critical path): out += h @ W_res via RED,
// concurrent with edge_kernel's RED accumulation (addition commutes).
// ---------------------------------------------------------------------------
__global__ __launch_bounds__(128, 4)
void resval_kernel(const float* __restrict__ h,
                   const float* __restrict__ Wres,
                   float* __restrict__ out)
{
    extern __shared__ float smem[];
    float* sW = smem;
    float* sT = smem + 4096;

    const int t   = threadIdx.x;
    const int nb0 = blockIdx.x * NPB;

    #pragma unroll
    for (int i = 0; i < 32; i++) sW[i * 128 + t] = Wres[i * 128 + t];

    {
        const int n = nb0 + t;
        #pragma unroll
        for (int k4 = 0; k4 < 16; k4++) {
            float4 v = make_float4(0.f, 0.f, 0.f, 0.f);
            if (n < NN) v = reinterpret_cast<const float4*>(h)[n * 16 + k4];
            sT[(k4 * 4 + 0) * 128 + t] = v.x;
            sT[(k4 * 4 + 1) * 128 + t] = v.y;
            sT[(k4 * 4 + 2) * 128 + t] = v.z;
            sT[(k4 * 4 + 3) * 128 + t] = v.w;
        }
    }
    __syncthreads();

    const int g    = t >> 2;
    const int head = t & 3;

    const float4* sT4 = reinterpret_cast<const float4*>(sT);
    const float4* sW4 = reinterpret_cast<const float4*>(sW);

    float acc[4][16];
    #pragma unroll
    for (int i = 0; i < 4; i++)
        #pragma unroll
        for (int j = 0; j < 16; j++) acc[i][j] = 0.f;

    #pragma unroll 4
    for (int k = 0; k < 64; k++) {
        float4 hv = sT4[k * 32 + g];
        float hvv[4] = {hv.x, hv.y, hv.z, hv.w};
        #pragma unroll
        for (int jq = 0; jq < 4; jq++) {
            float4 wv = sW4[k * 16 + head * 4 + jq];
            #pragma unroll
            for (int i = 0; i < 4; i++) {
                acc[i][jq * 4 + 0] += hvv[i] * wv.x;
                acc[i][jq * 4 + 1] += hvv[i] * wv.y;
                acc[i][jq * 4 + 2] += hvv[i] * wv.z;
                acc[i][jq * 4 + 3] += hvv[i] * wv.w;
            }
        }
    }

    #pragma unroll
    for (int i = 0; i < 4; i++) {
        const int n = nb0 + g * 4 + i;
        if (n < NN) {
            float* op = &out[n * 64 + head * 16];
            #pragma unroll
            for (int jq = 0; jq < 4; jq++) {
                asm volatile("red.global.add.v4.f32 [%0], {%1,%2,%3,%4};"
                             :: "l"(op + jq * 4),
                                "f"(acc[i][jq * 4 + 0]), "f"(acc[i][jq * 4 + 1]),
                                "f"(acc[i][jq * 4 + 2]), "f"(acc[i][jq * 4 + 3])
                             : "memory");
            }
        }
    }
}

// ---------------------------------------------------------------------------
// Edge kernel: 4 threads (one quad) per edge. Head-softmax via quad shuffles.
// fp16 feat gather (quad covers one 32 B sector per step); fp32 vector RED
// scatter (quad covers contiguous 64 B per step). At the L1-wavefront floor.
// ---------------------------------------------------------------------------
__global__ __launch_bounds__(256)
void edge_kernel(const void* __restrict__ src_raw,
                 const void* __restrict__ dst_raw,
                 float* __restrict__ out)
{
    const int t = blockIdx.x * 256 + threadIdx.x;
    const int e = t >> 2;
    if (e >= EE) return;
    const int q    = t & 3;
    const int lane = threadIdx.x & 31;

    int s, d;
    if (g_idx64) {
        s = (int)__ldg(&((const long long*)src_raw)[e]);
        d = (int)__ldg(&((const long long*)dst_raw)[e]);
    } else {
        s = __ldg(&((const int*)src_raw)[e]);
        d = __ldg(&((const int*)dst_raw)[e]);
    }

    float x = __ldg(&g_el[s * 4 + q]) + __ldg(&g_er[d * 4 + q]);
    x = (x > 0.f) ? x : 0.2f * x;                       // leaky relu

    float m = x;
    m = fmaxf(m, __shfl_xor_sync(0xFFFFFFFFu, m, 1));
    m = fmaxf(m, __shfl_xor_sync(0xFFFFFFFFu, m, 2));
    const float p = __expf(x - m);
    float ssum = p;
    ssum += __shfl_xor_sync(0xFFFFFFFFu, ssum, 1);
    ssum += __shfl_xor_sync(0xFFFFFFFFu, ssum, 2);
    const float a = p / ssum;

    const uint2* fh = reinterpret_cast<const uint2*>(g_feat + s * 64);
    float*       o  = out + d * 64;
    const int    qb = lane & ~3;

    #pragma unroll
    for (int j = 0; j < 4; j++) {
        const float aj = __shfl_sync(0xFFFFFFFFu, a, qb + j);
        const int   c  = j * 4 + q;
        const uint2 u  = __ldg(&fh[c]);
        const __half2 h0 = *reinterpret_cast<const __half2*>(&u.x);
        const __half2 h1 = *reinterpret_cast<const __half2*>(&u.y);
        const float2 f0 = __half22float2(h0);
        const float2 f1 = __half22float2(h1);
        asm volatile("red.global.add.v4.f32 [%0], {%1,%2,%3,%4};"
                     :: "l"(o + c * 4),
                        "f"(f0.x * aj), "f"(f0.y * aj), "f"(f1.x * aj), "f"(f1.y * aj)
                     : "memory");
    }
}

// ---------------------------------------------------------------------------
// Schedule:
//   s2 : zero_out ──► resval (RED into out) ──────────────┐
//   s1 : feat(fp16 mma) ─────► [wait zero] edge ──────────┴► join
// ---------------------------------------------------------------------------
extern "C" void kernel_launch(void* const* d_in, const int* in_sizes, int n_in,
                              void* d_out, int out_size)
{
    const float* h    = (const float*)d_in[0];
    const void*  src  = d_in[1];
    const void*  dst  = d_in[2];
    const float* Wfc  = (const float*)d_in[3];
    const float* al   = (const float*)d_in[4];
    const float* ar   = (const float*)d_in[5];
    const float* Wres = (const float*)d_in[6];
    float* out = (float*)d_out;

    const int feat_smem   = (128 * HS_H + 64 * WT_S) * 2 + 128 * (int)sizeof(float);
    const int resval_smem = (4096 + 64 * NPB) * (int)sizeof(float);

    // One-time host-side resources (no device memory involved).
    static bool         s_init = false;
    static cudaStream_t s2;
    static cudaEvent_t  evFork, evZero, evJoin;
    if (!s_init) {
        cudaStreamCreateWithFlags(&s2, cudaStreamNonBlocking);
        cudaEventCreateWithFlags(&evFork, cudaEventDisableTiming);
        cudaEventCreateWithFlags(&evZero, cudaEventDisableTiming);
        cudaEventCreateWithFlags(&evJoin, cudaEventDisableTiming);
        cudaFuncSetAttribute(feat_kernel,
                             cudaFuncAttributeMaxDynamicSharedMemorySize, feat_smem);
        cudaFuncSetAttribute(resval_kernel,
                             cudaFuncAttributeMaxDynamicSharedMemorySize, resval_smem);
        s_init = true;
    }

    const int node_blocks = (NN + NPB - 1) / NPB;               // 391

    // Fork s2: zero out, then resval RED-adds into it.
    cudaEventRecord(evFork, 0);
    cudaStreamWaitEvent(s2, evFork, 0);
    zero_kernel<<<(NN * 16 + 255) / 256, 256, 0, s2>>>((float4*)out);
    cudaEventRecord(evZero, s2);
    resval_kernel<<<node_blocks, 128, resval_smem, s2>>>(h, Wres, out);
    cudaEventRecord(evJoin, s2);

    // Main stream: feat, then edge (edge needs feat AND zeroed out).
    feat_kernel<<<node_blocks, 128, feat_smem>>>(h, Wfc, al, ar,
                                                 (const unsigned*)src);
    cudaStreamWaitEvent(0, evZero, 0);

    const int edge_blocks = (EE * 4) / 256;          // 12500 (exact)
    edge_kernel<<<edge_blocks, 256>>>(src, dst, out);

    // Join: resval must also be complete before the result is read.
    cudaStreamWaitEvent(0, evJoin, 0);
}